// round 1
// baseline (speedup 1.0000x reference)
#include <cuda_runtime.h>

#define HID  128
#define NH   8
#define NSEQ 4096
#define BP   4
#define SROW 4097   // h has 4097 rows per batch; last is hg

__device__ float g_u[BP*NH*HID];
__device__ float g_s[BP*NH*NSEQ];
__device__ float g_w[BP*NH*HID];
__device__ float g_mh[BP*HID];
__device__ float g_a[BP*NSEQ];
__device__ float g_bv[BP*NSEQ];

// ---------------- A: q = hg @ W_q ; u_h = W_k_head @ q_h ----------------
__global__ void kA(const float* __restrict__ h, const float* __restrict__ Wq,
                   const float* __restrict__ Wkv) {
    int b = blockIdx.x, t = threadIdx.x;           // 128 threads
    __shared__ float hg[HID], qs[HID];
    hg[t] = h[((size_t)b*SROW + NSEQ)*HID + t];
    __syncthreads();
    float q = 0.f;
    #pragma unroll 8
    for (int d = 0; d < HID; d++) q += hg[d]*Wq[d*HID + t];
    qs[t] = q;
    __syncthreads();
    #pragma unroll
    for (int hh = 0; hh < NH; hh++) {
        float u = 0.f;
        #pragma unroll
        for (int d = 0; d < 16; d++) u += Wkv[t*256 + hh*16 + d]*qs[hh*16 + d];
        g_u[(b*NH + hh)*HID + t] = u;
    }
}

// ---------------- B: s[b,h,n] = 0.25 * (hn[n] . u[b,h]) ----------------
__global__ void kB(const float* __restrict__ h) {
    int b = blockIdx.y;
    __shared__ float us[NH*HID];
    for (int i = threadIdx.x; i < NH*HID; i += blockDim.x) us[i] = g_u[b*NH*HID + i];
    __syncthreads();
    int warp = threadIdx.x >> 5, lane = threadIdx.x & 31;
    int row  = blockIdx.x*8 + warp;
    float4 hn4 = *(const float4*)&h[((size_t)b*SROW + row)*HID + lane*4];
    float acc[NH];
    #pragma unroll
    for (int hh = 0; hh < NH; hh++) {
        float4 u4 = *(const float4*)&us[hh*HID + lane*4];
        acc[hh] = hn4.x*u4.x + hn4.y*u4.y + hn4.z*u4.z + hn4.w*u4.w;
    }
    #pragma unroll
    for (int hh = 0; hh < NH; hh++) {
        float v = acc[hh];
        #pragma unroll
        for (int o = 16; o; o >>= 1) v += __shfl_xor_sync(0xffffffffu, v, o);
        if (lane == 0) g_s[(b*NH + hh)*NSEQ + row] = v*0.25f;
    }
}

// ------------ C: softmax over n per (b,h); w = sum_n p_n * hn[n] ------------
__global__ void kC(const float* __restrict__ h) {
    int hh = blockIdx.x, b = blockIdx.y, t = threadIdx.x;   // 512 threads
    __shared__ float p[NSEQ];
    __shared__ float red[512];
    __shared__ float wp[512];
    const float* srow = &g_s[(b*NH + hh)*NSEQ];

    float mx = -1e30f;
    for (int i = t; i < NSEQ; i += 512) { float v = srow[i]; p[i] = v; mx = fmaxf(mx, v); }
    red[t] = mx; __syncthreads();
    for (int o = 256; o; o >>= 1) { if (t < o) red[t] = fmaxf(red[t], red[t+o]); __syncthreads(); }
    mx = red[0]; __syncthreads();

    float sm = 0.f;
    for (int i = t; i < NSEQ; i += 512) { float e = expf(p[i]-mx); p[i] = e; sm += e; }
    red[t] = sm; __syncthreads();
    for (int o = 256; o; o >>= 1) { if (t < o) red[t] += red[t+o]; __syncthreads(); }
    float inv = 1.f/red[0];
    __syncthreads();

    int j = t & 127, slice = t >> 7;                 // 4 slices of 1024 tokens
    const float* hb = &h[(size_t)b*SROW*HID];
    float a0=0.f, a1=0.f, a2=0.f, a3=0.f;
    int n0 = slice*1024;
    for (int n = n0; n < n0 + 1024; n += 4) {
        a0 += p[n+0]*hb[(size_t)(n+0)*HID + j];
        a1 += p[n+1]*hb[(size_t)(n+1)*HID + j];
        a2 += p[n+2]*hb[(size_t)(n+2)*HID + j];
        a3 += p[n+3]*hb[(size_t)(n+3)*HID + j];
    }
    wp[t] = (a0+a1)+(a2+a3);
    __syncthreads();
    if (t < 128)
        g_w[(b*NH + hh)*HID + t] = (wp[t]+wp[t+128]+wp[t+256]+wp[t+384])*inv;
}

// ------------ D: y = w @ W_v_head ; mh = y @ W_mhc ------------
__global__ void kD(const float* __restrict__ Wkv, const float* __restrict__ Wmhc) {
    int b = blockIdx.x, t = threadIdx.x;             // 128 threads
    __shared__ float ws[NH*HID], ys[HID];
    for (int i = t; i < NH*HID; i += 128) ws[i] = g_w[b*NH*HID + i];
    __syncthreads();
    int hh = t >> 4;
    float y = 0.f;
    #pragma unroll 8
    for (int jj = 0; jj < HID; jj++) y += ws[hh*HID + jj]*Wkv[jj*256 + HID + t];
    ys[t] = y;
    __syncthreads();
    float m = 0.f;
    #pragma unroll 8
    for (int c = 0; c < HID; c++) m += ys[c]*Wmhc[c*HID + t];
    g_mh[b*HID + t] = m;
}

// ------------ E: y2[n] = mh . hn[n]; a = y2*w0, bv = y2*w1 ------------
__global__ void kE(const float* __restrict__ h, const float* __restrict__ Wlin) {
    int b = blockIdx.y;
    __shared__ float ms[HID];
    if (threadIdx.x < HID) ms[threadIdx.x] = g_mh[b*HID + threadIdx.x];
    __syncthreads();
    int warp = threadIdx.x >> 5, lane = threadIdx.x & 31;
    int row  = blockIdx.x*8 + warp;
    float4 hn4 = *(const float4*)&h[((size_t)b*SROW + row)*HID + lane*4];
    float4 m4  = *(const float4*)&ms[lane*4];
    float v = hn4.x*m4.x + hn4.y*m4.y + hn4.z*m4.z + hn4.w*m4.w;
    #pragma unroll
    for (int o = 16; o; o >>= 1) v += __shfl_xor_sync(0xffffffffu, v, o);
    if (lane == 0) {
        g_a [b*NSEQ + row] = v*Wlin[0];
        g_bv[b*NSEQ + row] = v*Wlin[1];
    }
}

// ------------ F: out[b, i*N + j] = a[b,j] + bv[b,i]  (256MB stream) ------------
__global__ void kF(float* __restrict__ out) {
    int b = blockIdx.y, i = blockIdx.x, t = threadIdx.x;   // 1024 threads, float4 each
    float bi = g_bv[b*NSEQ + i];
    float4 a4 = ((const float4*)&g_a[b*NSEQ])[t];
    float4 o4 = make_float4(a4.x+bi, a4.y+bi, a4.z+bi, a4.w+bi);
    ((float4*)&out[((size_t)b*NSEQ + i)*NSEQ])[t] = o4;
}

extern "C" void kernel_launch(void* const* d_in, const int* in_sizes, int n_in,
                              void* d_out, int out_size) {
    const float* h    = (const float*)d_in[0];
    const float* Wq   = (const float*)d_in[1];
    const float* Wkv  = (const float*)d_in[2];
    const float* Wmhc = (const float*)d_in[3];
    const float* Wlin = (const float*)d_in[4];
    float* out = (float*)d_out;

    kA<<<BP, 128>>>(h, Wq, Wkv);
    kB<<<dim3(NSEQ/8, BP), 256>>>(h);
    kC<<<dim3(NH, BP), 512>>>(h);
    kD<<<BP, 128>>>(Wkv, Wmhc);
    kE<<<dim3(NSEQ/8, BP), 256>>>(h, Wlin);
    kF<<<dim3(NSEQ, BP), 1024>>>(out);
}

// round 2
// speedup vs baseline: 1.8760x; 1.8760x over previous
#include <cuda_runtime.h>

#define HID  128
#define NH   8
#define NSEQ 4096
#define BP   4
#define SROW 4097   // h has 4097 rows per batch; last row is hg

__device__ float g_u[BP*NH*HID];
__device__ float g_s[BP*NH*NSEQ];
__device__ float g_w[BP*NH*HID];
__device__ float g_mh[BP*HID];
__device__ float g_a[BP*NSEQ];
__device__ float g_bv[BP*NSEQ];

// ---------------- A: q = hg @ W_q ; u_h = W_k_head @ q_h ----------------
// 512 threads/batch: each of 128 outputs computed by 4 thread-groups (k = tid>>7)
__global__ void kA(const float* __restrict__ h, const float* __restrict__ Wq,
                   const float* __restrict__ Wkv) {
    int b = blockIdx.x, tid = threadIdx.x;
    int t = tid & 127, k = tid >> 7;                 // t: output, k: quarter
    __shared__ float hg[HID], qp[4][HID], qs[HID];
    if (tid < HID) hg[tid] = h[((size_t)b*SROW + NSEQ)*HID + tid];
    __syncthreads();
    float q = 0.f;
    #pragma unroll
    for (int d = k*32; d < k*32 + 32; d++) q += hg[d]*Wq[d*HID + t];
    qp[k][t] = q;
    __syncthreads();
    if (tid < HID) qs[tid] = qp[0][tid] + qp[1][tid] + qp[2][tid] + qp[3][tid];
    __syncthreads();
    // u[hh][t], 1024 items / 512 threads = 2 each; 16-FMA dot
    #pragma unroll
    for (int it = 0; it < 2; it++) {
        int idx = tid + it*512;                      // 0..1023
        int hh = idx >> 7, tt = idx & 127;
        float u = 0.f;
        #pragma unroll
        for (int d = 0; d < 16; d++) u += Wkv[tt*256 + hh*16 + d]*qs[hh*16 + d];
        g_u[(b*NH + hh)*HID + tt] = u;
    }
}

// ---------------- B: s[b,h,n] = 0.25 * (hn[n] . u[b,h]) ----------------
__global__ void kB(const float* __restrict__ h) {
    int b = blockIdx.y;
    __shared__ float us[NH*HID];
    for (int i = threadIdx.x; i < NH*HID; i += blockDim.x) us[i] = g_u[b*NH*HID + i];
    __syncthreads();
    int warp = threadIdx.x >> 5, lane = threadIdx.x & 31;
    int row  = blockIdx.x*8 + warp;
    float4 hn4 = *(const float4*)&h[((size_t)b*SROW + row)*HID + lane*4];
    float acc[NH];
    #pragma unroll
    for (int hh = 0; hh < NH; hh++) {
        float4 u4 = *(const float4*)&us[hh*HID + lane*4];
        acc[hh] = hn4.x*u4.x + hn4.y*u4.y + hn4.z*u4.z + hn4.w*u4.w;
    }
    #pragma unroll
    for (int hh = 0; hh < NH; hh++) {
        float v = acc[hh];
        #pragma unroll
        for (int o = 16; o; o >>= 1) v += __shfl_xor_sync(0xffffffffu, v, o);
        if (lane == 0) g_s[(b*NH + hh)*NSEQ + row] = v*0.25f;
    }
}

// ---- C1: per (b,h): softmax-normalize scores in place; zero g_w ----
__global__ void kC1() {
    int hh = blockIdx.x, b = blockIdx.y, t = threadIdx.x;   // 512 threads
    __shared__ float red[512];
    float* srow = &g_s[(b*NH + hh)*NSEQ];
    float v[8];
    float mx = -1e30f;
    #pragma unroll
    for (int it = 0; it < 8; it++) { v[it] = srow[t + it*512]; mx = fmaxf(mx, v[it]); }
    red[t] = mx; __syncthreads();
    for (int o = 256; o; o >>= 1) { if (t < o) red[t] = fmaxf(red[t], red[t+o]); __syncthreads(); }
    mx = red[0]; __syncthreads();
    float sm = 0.f;
    #pragma unroll
    for (int it = 0; it < 8; it++) { v[it] = expf(v[it]-mx); sm += v[it]; }
    red[t] = sm; __syncthreads();
    for (int o = 256; o; o >>= 1) { if (t < o) red[t] += red[t+o]; __syncthreads(); }
    float inv = 1.f/red[0];
    #pragma unroll
    for (int it = 0; it < 8; it++) srow[t + it*512] = v[it]*inv;
    if (t < HID) g_w[(b*NH + hh)*HID + t] = 0.f;
}

// ---- C2: w[b,h,:] += sum over token chunk of p[b,h,n]*hn[n,:]  (1 read / 8 FMA) ----
#define CHUNK 128
__global__ void kC2(const float* __restrict__ h) {
    int b = blockIdx.y, c = blockIdx.x, j = threadIdx.x;    // 128 threads
    int n0 = c*CHUNK;
    __shared__ float ps[NH][CHUNK];
    #pragma unroll
    for (int it = 0; it < NH; it++) {
        int idx = j + it*128;                                // 0..1023
        int hh = idx / CHUNK, n = idx % CHUNK;
        ps[hh][n] = g_s[(b*NH + hh)*NSEQ + n0 + n];
    }
    __syncthreads();
    const float* hb = &h[((size_t)b*SROW + n0)*HID];
    float acc[NH] = {0,0,0,0,0,0,0,0};
    for (int n = 0; n < CHUNK; n++) {
        float hv = hb[(size_t)n*HID + j];
        #pragma unroll
        for (int hh = 0; hh < NH; hh++) acc[hh] += ps[hh][n]*hv;
    }
    #pragma unroll
    for (int hh = 0; hh < NH; hh++)
        atomicAdd(&g_w[(b*NH + hh)*HID + j], acc[hh]);
}

// ------------ D: y = w @ W_v_head ; mh = y @ W_mhc  (512 thr, split dots) ------------
__global__ void kD(const float* __restrict__ Wkv, const float* __restrict__ Wmhc) {
    int b = blockIdx.x, tid = threadIdx.x;
    int t = tid & 127, k = tid >> 7;
    __shared__ float ws[NH*HID], part[4][HID], ys[HID];
    for (int i = tid; i < NH*HID; i += 512) ws[i] = g_w[b*NH*HID + i];
    __syncthreads();
    int hh = t >> 4;
    float y = 0.f;
    #pragma unroll
    for (int jj = k*32; jj < k*32 + 32; jj++) y += ws[hh*HID + jj]*Wkv[jj*256 + HID + t];
    part[k][t] = y;
    __syncthreads();
    if (tid < HID) ys[tid] = part[0][tid] + part[1][tid] + part[2][tid] + part[3][tid];
    __syncthreads();
    float m = 0.f;
    #pragma unroll
    for (int c = k*32; c < k*32 + 32; c++) m += ys[c]*Wmhc[c*HID + t];
    part[k][t] = m;
    __syncthreads();
    if (tid < HID) g_mh[b*HID + tid] = part[0][tid] + part[1][tid] + part[2][tid] + part[3][tid];
}

// ------------ E: y2[n] = mh . hn[n]; a = y2*w0, bv = y2*w1 ------------
__global__ void kE(const float* __restrict__ h, const float* __restrict__ Wlin) {
    int b = blockIdx.y;
    __shared__ float ms[HID];
    if (threadIdx.x < HID) ms[threadIdx.x] = g_mh[b*HID + threadIdx.x];
    __syncthreads();
    int warp = threadIdx.x >> 5, lane = threadIdx.x & 31;
    int row  = blockIdx.x*8 + warp;
    float4 hn4 = *(const float4*)&h[((size_t)b*SROW + row)*HID + lane*4];
    float4 m4  = *(const float4*)&ms[lane*4];
    float v = hn4.x*m4.x + hn4.y*m4.y + hn4.z*m4.z + hn4.w*m4.w;
    #pragma unroll
    for (int o = 16; o; o >>= 1) v += __shfl_xor_sync(0xffffffffu, v, o);
    if (lane == 0) {
        g_a [b*NSEQ + row] = v*Wlin[0];
        g_bv[b*NSEQ + row] = v*Wlin[1];
    }
}

// ------------ F: out[b, i*N + j] = a[b,j] + bv[b,i]  (256MB stream) ------------
// Each block keeps its a-slice in registers and writes 8 rows: a-read traffic /8.
#define ROWS_F 8
__global__ void kF(float* __restrict__ out) {
    int b = blockIdx.y, t = threadIdx.x;                     // 1024 threads
    int i0 = blockIdx.x*ROWS_F;
    float4 a4 = ((const float4*)&g_a[b*NSEQ])[t];
    const float* bv = &g_bv[b*NSEQ];
    float4* ob = (float4*)&out[((size_t)b*NSEQ + i0)*NSEQ];
    #pragma unroll
    for (int r = 0; r < ROWS_F; r++) {
        float bi = bv[i0 + r];
        float4 o4 = make_float4(a4.x+bi, a4.y+bi, a4.z+bi, a4.w+bi);
        ob[(size_t)r*(NSEQ/4) + t] = o4;
    }
}

extern "C" void kernel_launch(void* const* d_in, const int* in_sizes, int n_in,
                              void* d_out, int out_size) {
    const float* h    = (const float*)d_in[0];
    const float* Wq   = (const float*)d_in[1];
    const float* Wkv  = (const float*)d_in[2];
    const float* Wmhc = (const float*)d_in[3];
    const float* Wlin = (const float*)d_in[4];
    float* out = (float*)d_out;

    kA <<<BP, 512>>>(h, Wq, Wkv);
    kB <<<dim3(NSEQ/8, BP), 256>>>(h);
    kC1<<<dim3(NH, BP), 512>>>();
    kC2<<<dim3(NSEQ/CHUNK, BP), 128>>>(h);
    kD <<<BP, 512>>>(Wkv, Wmhc);
    kE <<<dim3(NSEQ/8, BP), 256>>>(h, Wlin);
    kF <<<dim3(NSEQ/ROWS_F, BP), 1024>>>(out);
}

// round 3
// speedup vs baseline: 2.0680x; 1.1023x over previous
#include <cuda_runtime.h>

#define HID  128
#define NH   8
#define NSEQ 4096
#define BP   4
#define SROW 4097   // h has 4097 rows per batch; last row is hg

__device__ float g_u[BP*NH*HID];
__device__ float g_s[BP*NH*NSEQ];
__device__ float g_w[BP*NH*HID];
__device__ float g_mh[BP*HID];
__device__ float g_a[BP*NSEQ];
__device__ float g_bv[BP*NSEQ];

// ---------------- A: q = hg @ W_q ; u_h = W_k_head @ q_h ----------------
__global__ void kA(const float* __restrict__ h, const float* __restrict__ Wq,
                   const float* __restrict__ Wkv) {
    int b = blockIdx.x, tid = threadIdx.x;
    int t = tid & 127, k = tid >> 7;                 // t: output, k: quarter
    __shared__ float hg[HID], qp[4][HID], qs[HID];
    if (tid < HID) hg[tid] = h[((size_t)b*SROW + NSEQ)*HID + tid];
    __syncthreads();
    float q = 0.f;
    #pragma unroll
    for (int d = k*32; d < k*32 + 32; d++) q += hg[d]*Wq[d*HID + t];
    qp[k][t] = q;
    __syncthreads();
    if (tid < HID) qs[tid] = qp[0][tid] + qp[1][tid] + qp[2][tid] + qp[3][tid];
    __syncthreads();
    #pragma unroll
    for (int it = 0; it < 2; it++) {
        int idx = tid + it*512;                      // 0..1023
        int hh = idx >> 7, tt = idx & 127;
        float u = 0.f;
        #pragma unroll
        for (int d = 0; d < 16; d++) u += Wkv[tt*256 + hh*16 + d]*qs[hh*16 + d];
        g_u[(b*NH + hh)*HID + tt] = u;
    }
}

// ---------------- B: s[b,h,n] = 0.25 * (hn[n] . u[b,h]) ----------------
__global__ void kB(const float* __restrict__ h) {
    int b = blockIdx.y;
    __shared__ float us[NH*HID];
    for (int i = threadIdx.x; i < NH*HID; i += blockDim.x) us[i] = g_u[b*NH*HID + i];
    __syncthreads();
    int warp = threadIdx.x >> 5, lane = threadIdx.x & 31;
    int row  = blockIdx.x*8 + warp;
    float4 hn4 = *(const float4*)&h[((size_t)b*SROW + row)*HID + lane*4];
    float acc[NH];
    #pragma unroll
    for (int hh = 0; hh < NH; hh++) {
        float4 u4 = *(const float4*)&us[hh*HID + lane*4];
        acc[hh] = hn4.x*u4.x + hn4.y*u4.y + hn4.z*u4.z + hn4.w*u4.w;
    }
    #pragma unroll
    for (int hh = 0; hh < NH; hh++) {
        float v = acc[hh];
        #pragma unroll
        for (int o = 16; o; o >>= 1) v += __shfl_xor_sync(0xffffffffu, v, o);
        if (lane == 0) g_s[(b*NH + hh)*NSEQ + row] = v*0.25f;
    }
}

// ---- C1: per (b,h): softmax-normalize scores in place; zero g_w ----
__global__ void kC1() {
    int hh = blockIdx.x, b = blockIdx.y, t = threadIdx.x;   // 512 threads
    __shared__ float red[512];
    float* srow = &g_s[(b*NH + hh)*NSEQ];
    float v[8];
    float mx = -1e30f;
    #pragma unroll
    for (int it = 0; it < 8; it++) { v[it] = srow[t + it*512]; mx = fmaxf(mx, v[it]); }
    red[t] = mx; __syncthreads();
    for (int o = 256; o; o >>= 1) { if (t < o) red[t] = fmaxf(red[t], red[t+o]); __syncthreads(); }
    mx = red[0]; __syncthreads();
    float sm = 0.f;
    #pragma unroll
    for (int it = 0; it < 8; it++) { v[it] = expf(v[it]-mx); sm += v[it]; }
    red[t] = sm; __syncthreads();
    for (int o = 256; o; o >>= 1) { if (t < o) red[t] += red[t+o]; __syncthreads(); }
    float inv = 1.f/red[0];
    #pragma unroll
    for (int it = 0; it < 8; it++) srow[t + it*512] = v[it]*inv;
    if (t < HID) g_w[(b*NH + hh)*HID + t] = 0.f;
}

// ---- C2: w[b,h,:] += sum_n p[b,h,n]*hn[n,:]  (float4 loads, 8-deep MLP) ----
// grid (NSEQ/CHUNK, BP) x 256 threads. 32 lanes (float4 col groups) x 8 token slices.
#define CHUNK 64
__global__ void kC2(const float* __restrict__ h) {
    int b = blockIdx.y, c = blockIdx.x, tid = threadIdx.x;
    int lane = tid & 31, slice = tid >> 5;           // slice: 0..7, 8 tokens each
    __shared__ float ps[NH][CHUNK];
    #pragma unroll
    for (int i = tid; i < NH*CHUNK; i += 256) {
        int hh = i >> 6, n = i & 63;
        ps[hh][n] = g_s[(b*NH + hh)*NSEQ + c*CHUNK + n];
    }
    __syncthreads();
    const float* hb = &h[((size_t)b*SROW + c*CHUNK + slice*8)*HID];
    float4 acc[NH];
    #pragma unroll
    for (int hh = 0; hh < NH; hh++) acc[hh] = make_float4(0.f,0.f,0.f,0.f);
    #pragma unroll
    for (int n = 0; n < 8; n++) {
        float4 h4 = *(const float4*)&hb[(size_t)n*HID + lane*4];
        #pragma unroll
        for (int hh = 0; hh < NH; hh++) {
            float p = ps[hh][slice*8 + n];
            acc[hh].x += p*h4.x; acc[hh].y += p*h4.y;
            acc[hh].z += p*h4.z; acc[hh].w += p*h4.w;
        }
    }
    __shared__ float4 sm[8][NH][32];                 // 32KB
    #pragma unroll
    for (int hh = 0; hh < NH; hh++) sm[slice][hh][lane] = acc[hh];
    __syncthreads();
    // 256 float4 outputs / 256 threads = 1 each: sum 8 slices, atomic into g_w
    int hh = tid >> 5;
    float4 r = sm[0][hh][lane];
    #pragma unroll
    for (int s = 1; s < 8; s++) {
        float4 v = sm[s][hh][lane];
        r.x += v.x; r.y += v.y; r.z += v.z; r.w += v.w;
    }
    float* dst = &g_w[(b*NH + hh)*HID + lane*4];
    atomicAdd(dst+0, r.x); atomicAdd(dst+1, r.y);
    atomicAdd(dst+2, r.z); atomicAdd(dst+3, r.w);
}

// ------------ D: y = w @ W_v_head ; mh = y @ W_mhc  (512 thr, split dots) ------------
__global__ void kD(const float* __restrict__ Wkv, const float* __restrict__ Wmhc) {
    int b = blockIdx.x, tid = threadIdx.x;
    int t = tid & 127, k = tid >> 7;
    __shared__ float ws[NH*HID], part[4][HID], ys[HID];
    for (int i = tid; i < NH*HID; i += 512) ws[i] = g_w[b*NH*HID + i];
    __syncthreads();
    int hh = t >> 4;
    float y = 0.f;
    #pragma unroll
    for (int jj = k*32; jj < k*32 + 32; jj++) y += ws[hh*HID + jj]*Wkv[jj*256 + HID + t];
    part[k][t] = y;
    __syncthreads();
    if (tid < HID) ys[tid] = part[0][tid] + part[1][tid] + part[2][tid] + part[3][tid];
    __syncthreads();
    float m = 0.f;
    #pragma unroll
    for (int c = k*32; c < k*32 + 32; c++) m += ys[c]*Wmhc[c*HID + t];
    part[k][t] = m;
    __syncthreads();
    if (tid < HID) g_mh[b*HID + tid] = part[0][tid] + part[1][tid] + part[2][tid] + part[3][tid];
}

// ------------ E: y2[n] = mh . hn[n]; a = y2*w0, bv = y2*w1 ------------
__global__ void kE(const float* __restrict__ h, const float* __restrict__ Wlin) {
    int b = blockIdx.y;
    __shared__ float ms[HID];
    if (threadIdx.x < HID) ms[threadIdx.x] = g_mh[b*HID + threadIdx.x];
    __syncthreads();
    int warp = threadIdx.x >> 5, lane = threadIdx.x & 31;
    int row  = blockIdx.x*8 + warp;
    float4 hn4 = *(const float4*)&h[((size_t)b*SROW + row)*HID + lane*4];
    float4 m4  = *(const float4*)&ms[lane*4];
    float v = hn4.x*m4.x + hn4.y*m4.y + hn4.z*m4.z + hn4.w*m4.w;
    #pragma unroll
    for (int o = 16; o; o >>= 1) v += __shfl_xor_sync(0xffffffffu, v, o);
    if (lane == 0) {
        g_a [b*NSEQ + row] = v*Wlin[0];
        g_bv[b*NSEQ + row] = v*Wlin[1];
    }
}

// ------------ F: out[b, i*N + j] = a[b,j] + bv[b,i]  (256MB stream, wt stores) ------------
#define ROWS_F 8
__global__ void kF(float* __restrict__ out) {
    int b = blockIdx.y, t = threadIdx.x;                     // 1024 threads
    int i0 = blockIdx.x*ROWS_F;
    float4 a4 = ((const float4*)&g_a[b*NSEQ])[t];
    const float* bv = &g_bv[b*NSEQ];
    float4* ob = (float4*)&out[((size_t)b*NSEQ + i0)*NSEQ];
    #pragma unroll
    for (int r = 0; r < ROWS_F; r++) {
        float bi = bv[i0 + r];
        float4 o4 = make_float4(a4.x+bi, a4.y+bi, a4.z+bi, a4.w+bi);
        __stwt(&ob[(size_t)r*(NSEQ/4) + t], o4);
    }
}

extern "C" void kernel_launch(void* const* d_in, const int* in_sizes, int n_in,
                              void* d_out, int out_size) {
    const float* h    = (const float*)d_in[0];
    const float* Wq   = (const float*)d_in[1];
    const float* Wkv  = (const float*)d_in[2];
    const float* Wmhc = (const float*)d_in[3];
    const float* Wlin = (const float*)d_in[4];
    float* out = (float*)d_out;

    kA <<<BP, 512>>>(h, Wq, Wkv);
    kB <<<dim3(NSEQ/8, BP), 256>>>(h);
    kC1<<<dim3(NH, BP), 512>>>();
    kC2<<<dim3(NSEQ/CHUNK, BP), 256>>>(h);
    kD <<<BP, 512>>>(Wkv, Wmhc);
    kE <<<dim3(NSEQ/8, BP), 256>>>(h, Wlin);
    kF <<<dim3(NSEQ/ROWS_F, BP), 1024>>>(out);
}